// round 6
// baseline (speedup 1.0000x reference)
#include <cuda_runtime.h>
#include <math.h>

#define B_   2
#define S_   4096
#define E_   512
#define MTOT (B_ * S_)

// Scratch (allocation-free rule: __device__ globals)
__device__ float g_Q[(size_t)MTOT * E_];
__device__ float g_K[(size_t)MTOT * E_];
__device__ float g_V[(size_t)MTOT * E_];
__device__ float g_O[(size_t)MTOT * E_];
__device__ float g_P[(size_t)B_ * S_ * S_];   // scores, then probs in-place

// ---------------------------------------------------------------------------
// C[M,N] = alpha * A[M,K] * B[N,K]^T (+ bias[N]); optional upper-tri tile skip
// 128x128 tile, BK=8, 256 threads, 8x8 per thread.
// ---------------------------------------------------------------------------
__global__ __launch_bounds__(256) void gemm_nt(
    const float* __restrict__ A, const float* __restrict__ Bm,
    float* __restrict__ C, int M, int N, int K,
    float alpha, const float* __restrict__ bias,
    size_t sA, size_t sB, size_t sC, int tri)
{
    int bz = blockIdx.z;
    A  += (size_t)bz * sA;
    Bm += (size_t)bz * sB;
    C  += (size_t)bz * sC;
    int bx = blockIdx.x, by = blockIdx.y;
    if (tri && bx < by) return;   // tile entirely j < i -> masked, never read

    __shared__ float As[8][128];
    __shared__ float Bs[8][128];

    int tid  = threadIdx.x;
    int tx   = tid & 15;
    int ty   = tid >> 4;
    int lrow = tid >> 1;          // 0..127
    int lk   = (tid & 1) << 2;    // 0 or 4

    const float* Ap = A  + (size_t)(by * 128 + lrow) * K + lk;
    const float* Bp = Bm + (size_t)(bx * 128 + lrow) * K + lk;

    float acc[8][8] = {};

    for (int k0 = 0; k0 < K; k0 += 8) {
        float4 a4 = *(const float4*)(Ap + k0);
        float4 b4 = *(const float4*)(Bp + k0);
        __syncthreads();
        As[lk + 0][lrow] = a4.x; As[lk + 1][lrow] = a4.y;
        As[lk + 2][lrow] = a4.z; As[lk + 3][lrow] = a4.w;
        Bs[lk + 0][lrow] = b4.x; Bs[lk + 1][lrow] = b4.y;
        Bs[lk + 2][lrow] = b4.z; Bs[lk + 3][lrow] = b4.w;
        __syncthreads();
        #pragma unroll
        for (int kk = 0; kk < 8; ++kk) {
            float ar[8], br[8];
            *(float4*)&ar[0] = *(const float4*)&As[kk][ty * 8];
            *(float4*)&ar[4] = *(const float4*)&As[kk][ty * 8 + 4];
            *(float4*)&br[0] = *(const float4*)&Bs[kk][tx * 8];
            *(float4*)&br[4] = *(const float4*)&Bs[kk][tx * 8 + 4];
            #pragma unroll
            for (int i = 0; i < 8; ++i)
                #pragma unroll
                for (int j = 0; j < 8; ++j)
                    acc[i][j] += ar[i] * br[j];
        }
    }

    float bv[8];
    #pragma unroll
    for (int j = 0; j < 8; ++j)
        bv[j] = bias ? bias[bx * 128 + tx * 8 + j] : 0.f;

    #pragma unroll
    for (int i = 0; i < 8; ++i) {
        size_t row = (size_t)(by * 128 + ty * 8 + i);
        #pragma unroll
        for (int j = 0; j < 8; j += 4) {
            int col = bx * 128 + tx * 8 + j;
            float4 v;
            v.x = alpha * acc[i][j + 0] + bv[j + 0];
            v.y = alpha * acc[i][j + 1] + bv[j + 1];
            v.z = alpha * acc[i][j + 2] + bv[j + 2];
            v.w = alpha * acc[i][j + 3] + bv[j + 3];
            *(float4*)(C + row * N + col) = v;
        }
    }
}

// ---------------------------------------------------------------------------
// C[M,N] = A[M,K] * B[K,N]   (A = probs, zero for j < i)
// tri: start k-loop at by*128 (everything before is guaranteed zero in A)
// ---------------------------------------------------------------------------
__global__ __launch_bounds__(256) void gemm_nn_tri(
    const float* __restrict__ A, const float* __restrict__ Bm,
    float* __restrict__ C, int M, int N, int K,
    size_t sA, size_t sB, size_t sC, int tri)
{
    int bz = blockIdx.z;
    A  += (size_t)bz * sA;
    Bm += (size_t)bz * sB;
    C  += (size_t)bz * sC;
    int bx = blockIdx.x, by = blockIdx.y;

    __shared__ float As[8][128];
    __shared__ float Bs[8][128];

    int tid   = threadIdx.x;
    int tx    = tid & 15;
    int ty    = tid >> 4;
    int lrowA = tid >> 1;          // 0..127
    int lkA   = (tid & 1) << 2;    // 0 or 4
    int lrowB = tid >> 5;          // 0..7
    int lcolB = (tid & 31) << 2;   // 0..124

    int kstart = tri ? by * 128 : 0;

    const float* Ap = A  + (size_t)(by * 128 + lrowA) * K + lkA;
    const float* Bp = Bm + (size_t)lrowB * N + bx * 128 + lcolB;

    float acc[8][8] = {};

    for (int k0 = kstart; k0 < K; k0 += 8) {
        float4 a4 = *(const float4*)(Ap + k0);
        float4 b4 = *(const float4*)(Bp + (size_t)k0 * N);
        __syncthreads();
        As[lkA + 0][lrowA] = a4.x; As[lkA + 1][lrowA] = a4.y;
        As[lkA + 2][lrowA] = a4.z; As[lkA + 3][lrowA] = a4.w;
        *(float4*)&Bs[lrowB][lcolB] = b4;
        __syncthreads();
        #pragma unroll
        for (int kk = 0; kk < 8; ++kk) {
            float ar[8], br[8];
            *(float4*)&ar[0] = *(const float4*)&As[kk][ty * 8];
            *(float4*)&ar[4] = *(const float4*)&As[kk][ty * 8 + 4];
            *(float4*)&br[0] = *(const float4*)&Bs[kk][tx * 8];
            *(float4*)&br[4] = *(const float4*)&Bs[kk][tx * 8 + 4];
            #pragma unroll
            for (int i = 0; i < 8; ++i)
                #pragma unroll
                for (int j = 0; j < 8; ++j)
                    acc[i][j] += ar[i] * br[j];
        }
    }

    #pragma unroll
    for (int i = 0; i < 8; ++i) {
        size_t row = (size_t)(by * 128 + ty * 8 + i);
        #pragma unroll
        for (int j = 0; j < 8; j += 4) {
            int col = bx * 128 + tx * 8 + j;
            float4 v;
            v.x = acc[i][j + 0]; v.y = acc[i][j + 1];
            v.z = acc[i][j + 2]; v.w = acc[i][j + 3];
            *(float4*)(C + row * N + col) = v;
        }
    }
}

// ---------------------------------------------------------------------------
// In-place masked softmax over row i: keep j >= i, write 0 for j < i.
// One 256-thread block per (row, batch).
// ---------------------------------------------------------------------------
__global__ void softmax_anticausal(float* __restrict__ P, int Slen)
{
    int i = blockIdx.x;
    int b = blockIdx.y;
    float* row = P + ((size_t)b * Slen + i) * (size_t)Slen;
    int tid = threadIdx.x;
    __shared__ float red[256];

    float m = -INFINITY;
    for (int j = i + tid; j < Slen; j += 256) m = fmaxf(m, row[j]);
    red[tid] = m;
    __syncthreads();
    for (int s = 128; s > 0; s >>= 1) {
        if (tid < s) red[tid] = fmaxf(red[tid], red[tid + s]);
        __syncthreads();
    }
    m = red[0];
    __syncthreads();

    float sum = 0.f;
    for (int j = i + tid; j < Slen; j += 256) sum += expf(row[j] - m);
    red[tid] = sum;
    __syncthreads();
    for (int s = 128; s > 0; s >>= 1) {
        if (tid < s) red[tid] += red[tid + s];
        __syncthreads();
    }
    float inv = 1.0f / red[0];

    for (int j = tid; j < Slen; j += 256)
        row[j] = (j >= i) ? expf(row[j] - m) * inv : 0.f;
}

// ---------------------------------------------------------------------------
extern "C" void kernel_launch(void* const* d_in, const int* in_sizes, int n_in,
                              void* d_out, int out_size)
{
    (void)in_sizes; (void)n_in; (void)out_size;
    const float* x  = (const float*)d_in[0];
    const float* Wq = (const float*)d_in[1];
    const float* Wk = (const float*)d_in[2];
    const float* Wv = (const float*)d_in[3];
    const float* Wo = (const float*)d_in[4];
    const float* bo = (const float*)d_in[5];
    float* out = (float*)d_out;

    float *Q, *K, *V, *O, *P;
    cudaGetSymbolAddress((void**)&Q, g_Q);
    cudaGetSymbolAddress((void**)&K, g_K);
    cudaGetSymbolAddress((void**)&V, g_V);
    cudaGetSymbolAddress((void**)&O, g_O);
    cudaGetSymbolAddress((void**)&P, g_P);

    const float inv_scale = 1.0f / sqrtf((float)E_);
    dim3 blk(256);

    // Q/K/V projections: [8192,512] = x[8192,512] @ W^T
    dim3 gq(E_ / 128, MTOT / 128, 1);
    gemm_nt<<<gq, blk>>>(x, Wq, Q, MTOT, E_, E_, 1.f, nullptr, 0, 0, 0, 0);
    gemm_nt<<<gq, blk>>>(x, Wk, K, MTOT, E_, E_, 1.f, nullptr, 0, 0, 0, 0);
    gemm_nt<<<gq, blk>>>(x, Wv, V, MTOT, E_, E_, 1.f, nullptr, 0, 0, 0, 0);

    // scores[b] = inv_scale * Q[b] @ K[b]^T, upper-tri tiles only
    dim3 gs(S_ / 128, S_ / 128, B_);
    gemm_nt<<<gs, blk>>>(Q, K, P, S_, S_, E_, inv_scale, nullptr,
                         (size_t)S_ * E_, (size_t)S_ * E_, (size_t)S_ * S_, 1);

    // masked softmax (in place), zeros for j < i
    softmax_anticausal<<<dim3(S_, B_), blk>>>(P, S_);

    // O[b] = P[b] @ V[b], skipping all-zero leading k-tiles
    dim3 ga(E_ / 128, S_ / 128, B_);
    gemm_nn_tri<<<ga, blk>>>(P, V, O, S_, E_, S_,
                             (size_t)S_ * S_, (size_t)S_ * E_, (size_t)S_ * E_, 1);

    // final projection + bias
    gemm_nt<<<gq, blk>>>(O, Wo, out, MTOT, E_, E_, 1.f, bo, 0, 0, 0, 0);
}

// round 7
// speedup vs baseline: 1.0032x; 1.0032x over previous
#include <cuda_runtime.h>
#include <math.h>

#define B_   2
#define S_   4096
#define E_   512
#define MTOT (B_ * S_)

// Scratch (allocation-free rule: __device__ globals)
__device__ float g_Q[(size_t)MTOT * E_];
__device__ float g_K[(size_t)MTOT * E_];
__device__ float g_V[(size_t)MTOT * E_];
__device__ float g_O[(size_t)MTOT * E_];
__device__ float g_P[(size_t)B_ * S_ * S_];   // scores, then probs in-place

// ---------------------------------------------------------------------------
// C[M,N] = alpha * A[M,K] * B[N,K]^T (+ bias[N]); optional upper-tri tile skip
// 128x128 tile, BK=8, 256 threads, 8x8 per thread.
// ---------------------------------------------------------------------------
__global__ __launch_bounds__(256) void gemm_nt(
    const float* __restrict__ A, const float* __restrict__ Bm,
    float* __restrict__ C, int M, int N, int K,
    float alpha, const float* __restrict__ bias,
    size_t sA, size_t sB, size_t sC, int tri)
{
    int bz = blockIdx.z;
    A  += (size_t)bz * sA;
    Bm += (size_t)bz * sB;
    C  += (size_t)bz * sC;
    int bx = blockIdx.x, by = blockIdx.y;
    if (tri && bx < by) return;   // tile entirely j < i -> masked, never read

    __shared__ float As[8][128];
    __shared__ float Bs[8][128];

    int tid  = threadIdx.x;
    int tx   = tid & 15;
    int ty   = tid >> 4;
    int lrow = tid >> 1;          // 0..127
    int lk   = (tid & 1) << 2;    // 0 or 4

    const float* Ap = A  + (size_t)(by * 128 + lrow) * K + lk;
    const float* Bp = Bm + (size_t)(bx * 128 + lrow) * K + lk;

    float acc[8][8] = {};

    for (int k0 = 0; k0 < K; k0 += 8) {
        float4 a4 = *(const float4*)(Ap + k0);
        float4 b4 = *(const float4*)(Bp + k0);
        __syncthreads();
        As[lk + 0][lrow] = a4.x; As[lk + 1][lrow] = a4.y;
        As[lk + 2][lrow] = a4.z; As[lk + 3][lrow] = a4.w;
        Bs[lk + 0][lrow] = b4.x; Bs[lk + 1][lrow] = b4.y;
        Bs[lk + 2][lrow] = b4.z; Bs[lk + 3][lrow] = b4.w;
        __syncthreads();
        #pragma unroll
        for (int kk = 0; kk < 8; ++kk) {
            float ar[8], br[8];
            *(float4*)&ar[0] = *(const float4*)&As[kk][ty * 8];
            *(float4*)&ar[4] = *(const float4*)&As[kk][ty * 8 + 4];
            *(float4*)&br[0] = *(const float4*)&Bs[kk][tx * 8];
            *(float4*)&br[4] = *(const float4*)&Bs[kk][tx * 8 + 4];
            #pragma unroll
            for (int i = 0; i < 8; ++i)
                #pragma unroll
                for (int j = 0; j < 8; ++j)
                    acc[i][j] += ar[i] * br[j];
        }
    }

    float bv[8];
    #pragma unroll
    for (int j = 0; j < 8; ++j)
        bv[j] = bias ? bias[bx * 128 + tx * 8 + j] : 0.f;

    #pragma unroll
    for (int i = 0; i < 8; ++i) {
        size_t row = (size_t)(by * 128 + ty * 8 + i);
        #pragma unroll
        for (int j = 0; j < 8; j += 4) {
            int col = bx * 128 + tx * 8 + j;
            float4 v;
            v.x = alpha * acc[i][j + 0] + bv[j + 0];
            v.y = alpha * acc[i][j + 1] + bv[j + 1];
            v.z = alpha * acc[i][j + 2] + bv[j + 2];
            v.w = alpha * acc[i][j + 3] + bv[j + 3];
            *(float4*)(C + row * N + col) = v;
        }
    }
}

// ---------------------------------------------------------------------------
// C[M,N] = A[M,K] * B[K,N]   (A = probs, zero for j < i)
// tri: start k-loop at by*128 (everything before is guaranteed zero in A)
// ---------------------------------------------------------------------------
__global__ __launch_bounds__(256) void gemm_nn_tri(
    const float* __restrict__ A, const float* __restrict__ Bm,
    float* __restrict__ C, int M, int N, int K,
    size_t sA, size_t sB, size_t sC, int tri)
{
    int bz = blockIdx.z;
    A  += (size_t)bz * sA;
    Bm += (size_t)bz * sB;
    C  += (size_t)bz * sC;
    int bx = blockIdx.x, by = blockIdx.y;

    __shared__ float As[8][128];
    __shared__ float Bs[8][128];

    int tid   = threadIdx.x;
    int tx    = tid & 15;
    int ty    = tid >> 4;
    int lrowA = tid >> 1;          // 0..127
    int lkA   = (tid & 1) << 2;    // 0 or 4
    int lrowB = tid >> 5;          // 0..7
    int lcolB = (tid & 31) << 2;   // 0..124

    int kstart = tri ? by * 128 : 0;

    const float* Ap = A  + (size_t)(by * 128 + lrowA) * K + lkA;
    const float* Bp = Bm + (size_t)lrowB * N + bx * 128 + lcolB;

    float acc[8][8] = {};

    for (int k0 = kstart; k0 < K; k0 += 8) {
        float4 a4 = *(const float4*)(Ap + k0);
        float4 b4 = *(const float4*)(Bp + (size_t)k0 * N);
        __syncthreads();
        As[lkA + 0][lrowA] = a4.x; As[lkA + 1][lrowA] = a4.y;
        As[lkA + 2][lrowA] = a4.z; As[lkA + 3][lrowA] = a4.w;
        *(float4*)&Bs[lrowB][lcolB] = b4;
        __syncthreads();
        #pragma unroll
        for (int kk = 0; kk < 8; ++kk) {
            float ar[8], br[8];
            *(float4*)&ar[0] = *(const float4*)&As[kk][ty * 8];
            *(float4*)&ar[4] = *(const float4*)&As[kk][ty * 8 + 4];
            *(float4*)&br[0] = *(const float4*)&Bs[kk][tx * 8];
            *(float4*)&br[4] = *(const float4*)&Bs[kk][tx * 8 + 4];
            #pragma unroll
            for (int i = 0; i < 8; ++i)
                #pragma unroll
                for (int j = 0; j < 8; ++j)
                    acc[i][j] += ar[i] * br[j];
        }
    }

    #pragma unroll
    for (int i = 0; i < 8; ++i) {
        size_t row = (size_t)(by * 128 + ty * 8 + i);
        #pragma unroll
        for (int j = 0; j < 8; j += 4) {
            int col = bx * 128 + tx * 8 + j;
            float4 v;
            v.x = acc[i][j + 0]; v.y = acc[i][j + 1];
            v.z = acc[i][j + 2]; v.w = acc[i][j + 3];
            *(float4*)(C + row * N + col) = v;
        }
    }
}

// ---------------------------------------------------------------------------
// In-place masked softmax over row i: keep j >= i, write 0 for j < i.
// One 256-thread block per (row, batch).
// ---------------------------------------------------------------------------
__global__ void softmax_anticausal(float* __restrict__ P, int Slen)
{
    int i = blockIdx.x;
    int b = blockIdx.y;
    float* row = P + ((size_t)b * Slen + i) * (size_t)Slen;
    int tid = threadIdx.x;
    __shared__ float red[256];

    float m = -INFINITY;
    for (int j = i + tid; j < Slen; j += 256) m = fmaxf(m, row[j]);
    red[tid] = m;
    __syncthreads();
    for (int s = 128; s > 0; s >>= 1) {
        if (tid < s) red[tid] = fmaxf(red[tid], red[tid + s]);
        __syncthreads();
    }
    m = red[0];
    __syncthreads();

    float sum = 0.f;
    for (int j = i + tid; j < Slen; j += 256) sum += expf(row[j] - m);
    red[tid] = sum;
    __syncthreads();
    for (int s = 128; s > 0; s >>= 1) {
        if (tid < s) red[tid] += red[tid + s];
        __syncthreads();
    }
    float inv = 1.0f / red[0];

    for (int j = tid; j < Slen; j += 256)
        row[j] = (j >= i) ? expf(row[j] - m) * inv : 0.f;
}

// ---------------------------------------------------------------------------
extern "C" void kernel_launch(void* const* d_in, const int* in_sizes, int n_in,
                              void* d_out, int out_size)
{
    (void)in_sizes; (void)n_in; (void)out_size;
    const float* x  = (const float*)d_in[0];
    const float* Wq = (const float*)d_in[1];
    const float* Wk = (const float*)d_in[2];
    const float* Wv = (const float*)d_in[3];
    const float* Wo = (const float*)d_in[4];
    const float* bo = (const float*)d_in[5];
    float* out = (float*)d_out;

    float *Q, *K, *V, *O, *P;
    cudaGetSymbolAddress((void**)&Q, g_Q);
    cudaGetSymbolAddress((void**)&K, g_K);
    cudaGetSymbolAddress((void**)&V, g_V);
    cudaGetSymbolAddress((void**)&O, g_O);
    cudaGetSymbolAddress((void**)&P, g_P);

    const float inv_scale = 1.0f / sqrtf((float)E_);
    dim3 blk(256);

    // Q/K/V projections: [8192,512] = x[8192,512] @ W^T
    dim3 gq(E_ / 128, MTOT / 128, 1);
    gemm_nt<<<gq, blk>>>(x, Wq, Q, MTOT, E_, E_, 1.f, nullptr, 0, 0, 0, 0);
    gemm_nt<<<gq, blk>>>(x, Wk, K, MTOT, E_, E_, 1.f, nullptr, 0, 0, 0, 0);
    gemm_nt<<<gq, blk>>>(x, Wv, V, MTOT, E_, E_, 1.f, nullptr, 0, 0, 0, 0);

    // scores[b] = inv_scale * Q[b] @ K[b]^T, upper-tri tiles only
    dim3 gs(S_ / 128, S_ / 128, B_);
    gemm_nt<<<gs, blk>>>(Q, K, P, S_, S_, E_, inv_scale, nullptr,
                         (size_t)S_ * E_, (size_t)S_ * E_, (size_t)S_ * S_, 1);

    // masked softmax (in place), zeros for j < i
    softmax_anticausal<<<dim3(S_, B_), blk>>>(P, S_);

    // O[b] = P[b] @ V[b], skipping all-zero leading k-tiles
    dim3 ga(E_ / 128, S_ / 128, B_);
    gemm_nn_tri<<<ga, blk>>>(P, V, O, S_, E_, S_,
                             (size_t)S_ * S_, (size_t)S_ * E_, (size_t)S_ * E_, 1);

    // final projection + bias
    gemm_nt<<<gq, blk>>>(O, Wo, out, MTOT, E_, E_, 1.f, bo, 0, 0, 0, 0);
}